// round 8
// baseline (speedup 1.0000x reference)
#include <cuda_runtime.h>
#include <mma.h>
#include <cstdint>
#include <cstddef>

using namespace nvcuda;

#define B_  4
#define L_  1024
#define D_  1024
#define H_  16
#define DH_ 64
#define SD_ 30

// ---------------- scratch: __device__ globals (no allocation allowed) ----------------
__device__ float g_Q   [(size_t)B_*H_*L_*DH_];   // [bh][l][dh], pre-scaled by 1/8
__device__ float g_K   [(size_t)B_*H_*L_*DH_];
__device__ float g_V   [(size_t)B_*H_*L_*DH_];
__device__ float g_S   [(size_t)B_*H_*L_*L_];    // scores -> attn (in place), 256 MB
__device__ float g_qsk [(size_t)B_*H_*L_*31];    // [...,30] = q·bsk
__device__ float g_sattn[(size_t)B_*H_*L_*SD_];
__device__ float g_ctx [(size_t)B_*L_*D_];       // [b][q][h*64+d]
__device__ int   g_flags[2];                     // mask dtype detection

// ---------------- mask dtype detection ----------------
__global__ void reset_flags_k(){ g_flags[0]=0; g_flags[1]=0; }

// Reads exactly B*L*L/4 32-bit words = 4 MB, which equals the u8 buffer size
// (the smallest dtype candidate) -> never OOB for u8/i32/f32.
__global__ void detect_k(const unsigned* __restrict__ w, int n){
    int f0=0, f1=0;
    for (int i = blockIdx.x*blockDim.x + threadIdx.x; i < n; i += gridDim.x*blockDim.x){
        unsigned x = w[i];
        if (x == 0x3F800000u) f0 = 1;          // float 1.0f => f32 bool array
        else if (x & 0xFFFFFF00u) f1 = 1;      // nonzero high byte => u8 bool array
    }
    if (f0) atomicOr(&g_flags[0], 1);
    if (f1) atomicOr(&g_flags[1], 1);
}

__device__ __forceinline__ bool mread(const void* p, size_t i, int mode){
    if (mode == 2) return ((const float*)p)[i] != 0.f;
    if (mode == 1) return ((const int*)p)[i] != 0;
    return ((const unsigned char*)p)[i] != 0;
}

// ---------------- tf32 WMMA GEMM, CTA tile 128x64, K in steps of 16 ----------------
// 256 thr = 8 warps (4x2); warp tile 32x32 = 2x2 wmma 16x16x8 frags.
// Kt: total K. lda/ldb: row strides of A and B (both row-major).
// sA/sB: batch strides (z). bias may be null.
// EPI 0: C[m*D_+n]  (out projection)
// EPI 1: QKV proj scatter: C[((b*H+h)*L+l)*DH+dh], m=(b,l), n=(h,dh)
// EPI 2: ctx scatter: z=bh -> C[(b*L+m)*D + h*DH + n]
template<int EPI>
__global__ void __launch_bounds__(256)
gemm_tc(const float* __restrict__ A, const float* __restrict__ Bm,
        const float* __restrict__ bias, float* __restrict__ C, float scale,
        int Kt, int lda, int ldb, size_t sA, size_t sB)
{
    __shared__ union SmemU {
        struct { float As[128][16]; float Bs[16][72]; } s;   // load tiles
        float ep[128][72];                                   // epilogue tile
    } u;

    const int z = blockIdx.z;
    A  += (size_t)z * sA;
    Bm += (size_t)z * sB;
    const int bm = blockIdx.y * 128;
    const int bn = blockIdx.x * 64;
    const int tid = threadIdx.x;
    const int wid = tid >> 5;
    const int wm = (wid & 3) * 32;      // warp row offset in CTA tile
    const int wn = (wid >> 2) * 32;     // warp col offset

    wmma::fragment<wmma::accumulator, 16, 16, 8, float> c[2][2];
    #pragma unroll
    for (int i = 0; i < 2; i++)
        #pragma unroll
        for (int j = 0; j < 2; j++) wmma::fill_fragment(c[i][j], 0.f);

    for (int k0 = 0; k0 < Kt; k0 += 16){
        // A tile: 128 rows x 16 cols = 512 float4, 2 per thread
        #pragma unroll
        for (int t = tid; t < 512; t += 256){
            int r = t >> 2, c4 = (t & 3) * 4;
            *(float4*)&u.s.As[r][c4] = *(const float4*)&A[(size_t)(bm + r)*lda + k0 + c4];
        }
        // B tile: 16 rows x 64 cols = 256 float4, 1 per thread
        {
            int r = tid >> 4, c4 = (tid & 15) * 4;
            *(float4*)&u.s.Bs[r][c4] = *(const float4*)&Bm[(size_t)(k0 + r)*ldb + bn + c4];
        }
        __syncthreads();
        #pragma unroll
        for (int kk = 0; kk < 16; kk += 8){
            wmma::fragment<wmma::matrix_a, 16, 16, 8, wmma::precision::tf32, wmma::row_major> a[2];
            wmma::fragment<wmma::matrix_b, 16, 16, 8, wmma::precision::tf32, wmma::row_major> b[2];
            #pragma unroll
            for (int i = 0; i < 2; i++){
                wmma::load_matrix_sync(a[i], &u.s.As[wm + 16*i][kk], 16);
                #pragma unroll
                for (int t = 0; t < a[i].num_elements; t++)
                    a[i].x[t] = wmma::__float_to_tf32(a[i].x[t]);
            }
            #pragma unroll
            for (int j = 0; j < 2; j++){
                wmma::load_matrix_sync(b[j], &u.s.Bs[kk][wn + 16*j], 72);
                #pragma unroll
                for (int t = 0; t < b[j].num_elements; t++)
                    b[j].x[t] = wmma::__float_to_tf32(b[j].x[t]);
            }
            #pragma unroll
            for (int i = 0; i < 2; i++)
                #pragma unroll
                for (int j = 0; j < 2; j++)
                    wmma::mma_sync(c[i][j], a[i], b[j], c[i][j]);
        }
        __syncthreads();
    }

    // epilogue: frags -> smem -> global with bias/scale/EPI scatter
    #pragma unroll
    for (int i = 0; i < 2; i++)
        #pragma unroll
        for (int j = 0; j < 2; j++)
            wmma::store_matrix_sync(&u.ep[wm + 16*i][wn + 16*j], c[i][j], 72, wmma::mem_row_major);
    __syncthreads();

    #pragma unroll
    for (int t = tid; t < 128*64; t += 256){
        const int r = t >> 6, cc = t & 63;
        const int m = bm + r, n = bn + cc;
        float v = u.ep[r][cc];
        if (bias) v += bias[n];
        v *= scale;
        if (EPI == 0){
            C[(size_t)m*D_ + n] = v;
        } else if (EPI == 1){
            const int b = m >> 10, l = m & (L_-1);
            const int h = n >> 6,  dh = n & (DH_-1);
            C[((size_t)(b*H_+h)*L_ + l)*DH_ + dh] = v;
        } else {
            const int b = z >> 4, h = z & (H_-1);
            C[((size_t)(b*L_ + m))*D_ + h*DH_ + cc] = v;
        }
    }
}

// ---------------- generic tiled fp32 GEMM (QK^T only; precision-critical) ----------------
// C = (A @ B) * scale ; batched (z) with strides. TRANSB: B is [N][K] row-major.
template<int BM,int BN,int BK,int TM,int TN>
__global__ void __launch_bounds__(256)
gemm_qk(const float* __restrict__ A, const float* __restrict__ Bm,
        float* __restrict__ C, int K,
        size_t sA, size_t sB, size_t sC)
{
    constexpr int NTHR = (BM/TM)*(BN/TN);
    __shared__ float As[BK][BM];
    __shared__ float Bs[BK][BN];
    const int z  = blockIdx.z;
    A  += (size_t)z * sA;
    Bm += (size_t)z * sB;
    const int bm = blockIdx.y * BM;
    const int bn = blockIdx.x * BN;
    const int tid = threadIdx.x;
    const int tx = tid % (BN/TN);
    const int ty = tid / (BN/TN);

    float acc[TM][TN];
    #pragma unroll
    for (int i=0;i<TM;i++)
        #pragma unroll
        for (int j=0;j<TN;j++) acc[i][j] = 0.f;

    for (int k0 = 0; k0 < K; k0 += BK){
        #pragma unroll
        for (int t = tid; t < BM*BK/4; t += NTHR){
            int r = t / (BK/4);
            int c = (t % (BK/4)) * 4;
            float4 v = *(const float4*)&A[(size_t)(bm+r)*K + k0 + c];
            As[c+0][r]=v.x; As[c+1][r]=v.y; As[c+2][r]=v.z; As[c+3][r]=v.w;
        }
        #pragma unroll
        for (int t = tid; t < BN*BK/4; t += NTHR){
            int r = t / (BK/4);
            int c = (t % (BK/4)) * 4;
            float4 v = *(const float4*)&Bm[(size_t)(bn+r)*K + k0 + c];
            Bs[c+0][r]=v.x; Bs[c+1][r]=v.y; Bs[c+2][r]=v.z; Bs[c+3][r]=v.w;
        }
        __syncthreads();
        #pragma unroll
        for (int kk = 0; kk < BK; kk++){
            float ra[TM], rb[TN];
            #pragma unroll
            for (int i=0;i<TM;i++) ra[i] = As[kk][ty*TM+i];
            #pragma unroll
            for (int j=0;j<TN;j++) rb[j] = Bs[kk][tx*TN+j];
            #pragma unroll
            for (int i=0;i<TM;i++)
                #pragma unroll
                for (int j=0;j<TN;j++) acc[i][j] += ra[i]*rb[j];
        }
        __syncthreads();
    }

    #pragma unroll
    for (int i=0;i<TM;i++){
        const int m = bm + ty*TM + i;
        #pragma unroll
        for (int j=0;j<TN;j++){
            const int n = bn + tx*TN + j;
            C[(size_t)z*sC + (size_t)m*(size_t)gridDim.x/1*0 + (size_t)m*L_ + n] = acc[i][j];
        }
    }
}

// ---------------- qsk[b,h,q,s] = sum_d Q[bh,q,d]*Wsk[s,d]; slot 30 = Q·bsk ----------------
__global__ void qsk_k(const float* __restrict__ Wsk, const float* __restrict__ bsk){
    const int s   = threadIdx.x;                 // 0..31
    const int row = blockIdx.x*8 + threadIdx.y;  // bh*L + q
    if (s >= 31) return;
    const float* qp = g_Q + (size_t)row * DH_;
    const float* wp = (s < SD_) ? (Wsk + s*DH_) : bsk;
    float a = 0.f;
    #pragma unroll
    for (int d = 0; d < DH_; d++) a += qp[d]*wp[d];
    g_qsk[(size_t)row*31 + s] = a;
}

// ---------------- scores += ALPHA*(struct·qsk + q·bsk); apply masks ----------------
__global__ void __launch_bounds__(256)
bias_mask_k(const float* __restrict__ st, const void* __restrict__ mask,
            const void* __restrict__ kpm)
{
    const int b = blockIdx.z, q = blockIdx.y;
    const int k = blockIdx.x*256 + threadIdx.x;
    const int tid = threadIdx.x;
    __shared__ float qs[H_][32];
    for (int t = tid; t < H_*31; t += 256){
        int h = t/31, s = t%31;
        qs[h][s] = g_qsk[((size_t)((b*H_+h)*L_ + q))*31 + s];
    }
    __syncthreads();
    const int fm = g_flags[0] ? 2 : (g_flags[1] ? 0 : 1);
    const bool masked = mread(kpm, (size_t)b*L_ + k, fm)
                     || mread(mask, ((size_t)(b*L_+q))*L_ + k, fm);
    float r[SD_];
    const float* sp = st + ((size_t)((b*L_+q))*L_ + k) * SD_;
    #pragma unroll
    for (int i = 0; i < 15; i++){
        float2 u = *(const float2*)(sp + 2*i);
        r[2*i] = u.x; r[2*i+1] = u.y;
    }
    #pragma unroll
    for (int h = 0; h < H_; h++){
        float a = qs[h][30];                 // q·bsk term
        #pragma unroll
        for (int s = 0; s < SD_; s++) a += qs[h][s]*r[s];
        size_t si = ((size_t)((b*H_+h)*L_ + q))*L_ + k;
        float val = g_S[si] + a;             // ALPHA = 1
        g_S[si] = masked ? -1e18f : val;
    }
}

// ---------------- row softmax over k; stream head-0 rows to top_attn ----------------
__global__ void __launch_bounds__(256)
softmax_k(float* __restrict__ top){
    const int row = blockIdx.x;                  // bh*L + q
    const int bh = row >> 10, q = row & (L_-1);
    float* p = g_S + (size_t)row * L_;
    const int tid = threadIdx.x;
    float v[4];
    float mx = -3.4e38f;
    #pragma unroll
    for (int i=0;i<4;i++){ v[i] = p[tid + i*256]; mx = fmaxf(mx, v[i]); }
    __shared__ float red[8];
    #pragma unroll
    for (int o=16;o>0;o>>=1) mx = fmaxf(mx, __shfl_xor_sync(0xffffffffu, mx, o));
    if ((tid & 31) == 0) red[tid>>5] = mx;
    __syncthreads();
    float m2 = red[0];
    #pragma unroll
    for (int i=1;i<8;i++) m2 = fmaxf(m2, red[i]);
    float sum = 0.f;
    #pragma unroll
    for (int i=0;i<4;i++){ v[i] = __expf(v[i]-m2); sum += v[i]; }
    __syncthreads();
    #pragma unroll
    for (int o=16;o>0;o>>=1) sum += __shfl_xor_sync(0xffffffffu, sum, o);
    if ((tid & 31) == 0) red[tid>>5] = sum;
    __syncthreads();
    float s2 = 0.f;
    #pragma unroll
    for (int i=0;i<8;i++) s2 += red[i];
    const float inv = 1.f / s2;
    const bool isTop = (bh & (H_-1)) == 0;
    float* tp = top + ((size_t)((bh>>4)*L_ + q))*L_;
    #pragma unroll
    for (int i=0;i<4;i++){
        float a = v[i]*inv;
        p[tid + i*256] = a;
        if (isTop) tp[tid + i*256] = a;
    }
}

// ---------------- sattn[b,h,q,s] = sum_k attn[bh,q,k]*struct[b,q,k,s] ----------------
__global__ void __launch_bounds__(256)
sattn_k(const float* __restrict__ st){
    const int bq = blockIdx.x;
    const int b = bq >> 10, q = bq & (L_-1);
    const int tid = threadIdx.x;
    const int h = tid/15, sp = tid%15;
    const bool act = tid < 240;
    float a0 = 0.f, a1 = 0.f;
    __shared__ float attn_s[H_][256];
    for (int kt = 0; kt < L_; kt += 256){
        __syncthreads();
        for (int i = tid; i < H_*256; i += 256){
            int hh = i>>8, kk = i&255;
            attn_s[hh][kk] = g_S[((size_t)((b*H_+hh)*L_ + q))*L_ + kt + kk];
        }
        __syncthreads();
        if (act){
            const float* s2 = st + ((size_t)(bq)*L_ + kt)*SD_ + sp*2;
            #pragma unroll 4
            for (int kk = 0; kk < 256; kk++){
                float av = attn_s[h][kk];
                float2 u = __ldg((const float2*)(s2 + (size_t)kk*SD_));
                a0 += av*u.x; a1 += av*u.y;
            }
        }
    }
    if (act){
        size_t o = ((size_t)((b*H_+h)*L_ + q))*SD_ + sp*2;
        g_sattn[o] = a0; g_sattn[o+1] = a1;
    }
}

// ---------------- ctx += BETA*(sattn @ Wsv + bsv)  (sum attn = 1) ----------------
__global__ void __launch_bounds__(256)
addctx_k(const float* __restrict__ Wsv, const float* __restrict__ bsv){
    const int bq = blockIdx.x;
    const int b = bq >> 10, q = bq & (L_-1);
    const int tid = threadIdx.x;
    __shared__ float sa[H_][SD_];
    for (int i = tid; i < H_*SD_; i += 256){
        int h = i/SD_, s = i%SD_;
        sa[h][s] = g_sattn[((size_t)((b*H_+h)*L_ + q))*SD_ + s];
    }
    __syncthreads();
    #pragma unroll
    for (int rep = 0; rep < 4; rep++){
        int hd = rep*256 + tid;
        int h = hd >> 6, d = hd & (DH_-1);
        float a = bsv[d];
        #pragma unroll
        for (int s = 0; s < SD_; s++) a += sa[h][s]*Wsv[s*DH_+d];
        g_ctx[(size_t)bq*D_ + hd] += a;      // BETA = 1
    }
}

// ---------------- launcher ----------------
extern "C" void kernel_launch(void* const* d_in, const int* in_sizes, int n_in,
                              void* d_out, int out_size)
{
    const float* key       = (const float*)d_in[0];
    const float* value     = (const float*)d_in[1];
    const float* query     = (const float*)d_in[2];
    const float* structure = (const float*)d_in[3];
    const void*  mask      = d_in[4];
    const void*  kpm       = d_in[5];
    const float* Wq  = (const float*)d_in[6];
    const float* bq  = (const float*)d_in[7];
    const float* Wk  = (const float*)d_in[8];
    const float* bk  = (const float*)d_in[9];
    const float* Wv  = (const float*)d_in[10];
    const float* bv  = (const float*)d_in[11];
    const float* Wsk = (const float*)d_in[12];
    const float* bsk = (const float*)d_in[13];
    const float* Wsv = (const float*)d_in[14];
    const float* bsv = (const float*)d_in[15];
    const float* Wo  = (const float*)d_in[16];
    const float* bo  = (const float*)d_in[17];

    float* out = (float*)d_out;
    float* top = out + (size_t)B_*L_*D_;

    float *pQ, *pK, *pV, *pS, *pCtx;
    cudaGetSymbolAddress((void**)&pQ,   g_Q);
    cudaGetSymbolAddress((void**)&pK,   g_K);
    cudaGetSymbolAddress((void**)&pV,   g_V);
    cudaGetSymbolAddress((void**)&pS,   g_S);
    cudaGetSymbolAddress((void**)&pCtx, g_ctx);

    // mask dtype detection
    reset_flags_k<<<1,1>>>();
    detect_k<<<2048,256>>>((const unsigned*)mask, B_*L_*L_/4);

    // QKV projections, tf32 tensor cores (EPI=1 scatter to [bh][l][dh]); Q pre-scaled
    dim3 gtc(D_/64, (B_*L_)/128, 1);
    gemm_tc<1><<<gtc,256>>>(query, Wq, bq, pQ, 0.125f, D_, D_, D_, 0, 0);
    gemm_tc<1><<<gtc,256>>>(key,   Wk, bk, pK, 1.0f,   D_, D_, D_, 0, 0);
    gemm_tc<1><<<gtc,256>>>(value, Wv, bv, pV, 1.0f,   D_, D_, D_, 0, 0);

    // qsk = Q @ Wsk^T (+ Q·bsk in slot 30)
    qsk_k<<<(B_*H_*L_)/8, dim3(32,8)>>>(Wsk, bsk);

    // scores = Q @ K^T (batched over bh, fp32 SIMT — precision-critical for top_attn)
    gemm_qk<128,128,8,8,8><<<dim3(L_/128, L_/128, B_*H_),256>>>(
        pQ, pK, pS, DH_,
        (size_t)L_*DH_, (size_t)L_*DH_, (size_t)L_*L_);

    // + struct bias, masks
    bias_mask_k<<<dim3(L_/256, L_, B_),256>>>(structure, mask, kpm);

    // softmax (writes attn in place, head-0 rows to top_attn)
    softmax_k<<<B_*H_*L_,256>>>(top);

    // ctx = attn @ V, tf32 tensor cores (EPI=2 scatter), batched over bh
    gemm_tc<2><<<dim3(1, L_/128, B_*H_),256>>>(
        pS, pV, (const float*)nullptr, pCtx, 1.0f,
        L_, L_, DH_, (size_t)L_*L_, (size_t)L_*DH_);

    // sattn = attn @ struct ; ctx += sattn @ Wsv + bsv
    sattn_k<<<B_*L_,256>>>(structure);
    addctx_k<<<B_*L_,256>>>(Wsv, bsv);

    // output = ctx @ Wo + bo, tf32 tensor cores
    gemm_tc<0><<<gtc,256>>>(pCtx, Wo, bo, out, 1.0f, D_, D_, D_, 0, 0);
}

// round 13
// speedup vs baseline: 1.0846x; 1.0846x over previous
#include <cuda_runtime.h>
#include <mma.h>
#include <cstdint>
#include <cstddef>

using namespace nvcuda;

#define B_  4
#define L_  1024
#define D_  1024
#define H_  16
#define DH_ 64
#define SD_ 30

// ---------------- scratch: __device__ globals (no allocation allowed) ----------------
__device__ float g_Q   [(size_t)B_*H_*L_*DH_];   // [bh][l][dh], pre-scaled by 1/8
__device__ float g_K   [(size_t)B_*H_*L_*DH_];
__device__ float g_V   [(size_t)B_*H_*L_*DH_];
__device__ float g_S   [(size_t)B_*H_*L_*L_];    // scores -> attn (in place), 256 MB
__device__ float g_qsk [(size_t)B_*H_*L_*31];    // [...,30] = q·bsk
__device__ float g_sattn[(size_t)B_*H_*L_*SD_];
__device__ float g_ctx [(size_t)B_*L_*D_];       // [b][q][h*64+d]
__device__ int   g_flags[2];                     // mask dtype detection

// ---------------- mask dtype detection ----------------
__global__ void reset_flags_k(){ g_flags[0]=0; g_flags[1]=0; }

__global__ void detect_k(const unsigned* __restrict__ w, int n){
    int f0=0, f1=0;
    for (int i = blockIdx.x*blockDim.x + threadIdx.x; i < n; i += gridDim.x*blockDim.x){
        unsigned x = w[i];
        if (x == 0x3F800000u) f0 = 1;          // float 1.0f => f32 bool array
        else if (x & 0xFFFFFF00u) f1 = 1;      // nonzero high byte => u8 bool array
    }
    if (f0) atomicOr(&g_flags[0], 1);
    if (f1) atomicOr(&g_flags[1], 1);
}

__device__ __forceinline__ bool mread(const void* p, size_t i, int mode){
    if (mode == 2) return ((const float*)p)[i] != 0.f;
    if (mode == 1) return ((const int*)p)[i] != 0;
    return ((const unsigned char*)p)[i] != 0;
}

// ---------------- tf32 WMMA GEMM v2: CTA 128x128, warp tile 64x32 ----------------
// Fixed shape M=4096, N=1024, K=1024. A [M][K] row-major, B [K][N] row-major.
// tf32 conversion happens ONCE during smem fill. A-tile padded to 20 cols to
// spread rows across banks. Two-pass epilogue via 128x72 smem buffer.
// EPI 0: C[m*D_+n].  EPI 1: QKV scatter C[((b*H+h)*L+l)*DH+dh].
template<int EPI>
__global__ void __launch_bounds__(256)
gemm_tc2(const float* __restrict__ A, const float* __restrict__ Bm,
         const float* __restrict__ bias, float* __restrict__ C, float scale)
{
    __shared__ union SmemU {
        struct { float As[128][20]; float Bs[16][136]; } s;
        float ep[128][72];
    } u;

    const int bm = blockIdx.y * 128;
    const int bn = blockIdx.x * 128;
    const int tid = threadIdx.x;
    const int wid = tid >> 5;
    const int wm = (wid & 1) * 64;     // 2 m-tiles of 64
    const int wn = (wid >> 1) * 32;    // 4 n-tiles of 32

    wmma::fragment<wmma::accumulator, 16, 16, 8, float> c[4][2];
    #pragma unroll
    for (int i = 0; i < 4; i++)
        #pragma unroll
        for (int j = 0; j < 2; j++) wmma::fill_fragment(c[i][j], 0.f);

    for (int k0 = 0; k0 < D_; k0 += 16){
        // A tile: 128 rows x 16 cols = 512 float4, 2/thread, cvt on store
        #pragma unroll
        for (int t = tid; t < 512; t += 256){
            int r = t >> 2, c4 = (t & 3) * 4;
            float4 v = *(const float4*)&A[(size_t)(bm + r)*D_ + k0 + c4];
            u.s.As[r][c4+0] = wmma::__float_to_tf32(v.x);
            u.s.As[r][c4+1] = wmma::__float_to_tf32(v.y);
            u.s.As[r][c4+2] = wmma::__float_to_tf32(v.z);
            u.s.As[r][c4+3] = wmma::__float_to_tf32(v.w);
        }
        // B tile: 16 rows x 128 cols = 512 float4, 2/thread, cvt on store
        #pragma unroll
        for (int t = tid; t < 512; t += 256){
            int r = t >> 5, c4 = (t & 31) * 4;
            float4 v = *(const float4*)&Bm[(size_t)(k0 + r)*D_ + bn + c4];
            u.s.Bs[r][c4+0] = wmma::__float_to_tf32(v.x);
            u.s.Bs[r][c4+1] = wmma::__float_to_tf32(v.y);
            u.s.Bs[r][c4+2] = wmma::__float_to_tf32(v.z);
            u.s.Bs[r][c4+3] = wmma::__float_to_tf32(v.w);
        }
        __syncthreads();
        #pragma unroll
        for (int kk = 0; kk < 16; kk += 8){
            wmma::fragment<wmma::matrix_a, 16, 16, 8, wmma::precision::tf32, wmma::row_major> a[4];
            wmma::fragment<wmma::matrix_b, 16, 16, 8, wmma::precision::tf32, wmma::row_major> b[2];
            #pragma unroll
            for (int i = 0; i < 4; i++)
                wmma::load_matrix_sync(a[i], &u.s.As[wm + 16*i][kk], 20);
            #pragma unroll
            for (int j = 0; j < 2; j++)
                wmma::load_matrix_sync(b[j], &u.s.Bs[kk][wn + 16*j], 136);
            #pragma unroll
            for (int i = 0; i < 4; i++)
                #pragma unroll
                for (int j = 0; j < 2; j++)
                    wmma::mma_sync(c[i][j], a[i], b[j], c[i][j]);
        }
        __syncthreads();
    }

    // two-pass epilogue: n-halves [0,64) then [64,128)
    #pragma unroll
    for (int pass = 0; pass < 2; pass++){
        if ((wn >= 64) == (pass == 1)){
            const int wnl = wn - 64*pass;
            #pragma unroll
            for (int i = 0; i < 4; i++)
                #pragma unroll
                for (int j = 0; j < 2; j++)
                    wmma::store_matrix_sync(&u.ep[wm + 16*i][wnl + 16*j], c[i][j], 72,
                                            wmma::mem_row_major);
        }
        __syncthreads();
        #pragma unroll
        for (int t = tid; t < 128*64; t += 256){
            const int r = t >> 6, cc = t & 63;
            const int m = bm + r, n = bn + pass*64 + cc;
            float v = (u.ep[r][cc] + bias[n]) * scale;
            if (EPI == 0){
                C[(size_t)m*D_ + n] = v;
            } else {
                const int b = m >> 10, l = m & (L_-1);
                const int h = n >> 6,  dh = n & (DH_-1);
                C[((size_t)(b*H_+h)*L_ + l)*DH_ + dh] = v;
            }
        }
        __syncthreads();
    }
}

// ---------------- QK^T via 3xTF32 (near-fp32 precision on tensor cores) ----------------
// S[z][m][n] = sum_k Q[z][m][k]*K[z][n][k], K=64. CTA 128m x 64n, warp 32x32.
// big = tf32(x), small = tf32(x - big); c += ab*bb + ab*bs + as*bb (error ~2^-21).
__global__ void __launch_bounds__(256)
qk_tc(const float* __restrict__ Q, const float* __restrict__ Km, float* __restrict__ S)
{
    __shared__ float Ab[128][20], As[128][20], Bb[64][20], Bs[64][20];
    const int z = blockIdx.z;
    const float* Aq = Q  + (size_t)z * L_ * DH_;
    const float* Bk = Km + (size_t)z * L_ * DH_;
    float* Sp = S + (size_t)z * L_ * L_;
    const int bm = blockIdx.y * 128;
    const int bn = blockIdx.x * 64;
    const int tid = threadIdx.x;
    const int wid = tid >> 5;
    const int wm = (wid & 3) * 32;     // 4 m-tiles
    const int wn = (wid >> 2) * 32;    // 2 n-tiles

    wmma::fragment<wmma::accumulator, 16, 16, 8, float> c[2][2];
    #pragma unroll
    for (int i = 0; i < 2; i++)
        #pragma unroll
        for (int j = 0; j < 2; j++) wmma::fill_fragment(c[i][j], 0.f);

    for (int k0 = 0; k0 < DH_; k0 += 16){
        // Q tile: 128 rows x 16 cols, split big/small
        #pragma unroll
        for (int t = tid; t < 512; t += 256){
            int r = t >> 2, c4 = (t & 3) * 4;
            float4 v = *(const float4*)&Aq[(size_t)(bm + r)*DH_ + k0 + c4];
            float b0 = wmma::__float_to_tf32(v.x);
            float b1 = wmma::__float_to_tf32(v.y);
            float b2 = wmma::__float_to_tf32(v.z);
            float b3 = wmma::__float_to_tf32(v.w);
            Ab[r][c4+0]=b0; As[r][c4+0]=wmma::__float_to_tf32(v.x - b0);
            Ab[r][c4+1]=b1; As[r][c4+1]=wmma::__float_to_tf32(v.y - b1);
            Ab[r][c4+2]=b2; As[r][c4+2]=wmma::__float_to_tf32(v.z - b2);
            Ab[r][c4+3]=b3; As[r][c4+3]=wmma::__float_to_tf32(v.w - b3);
        }
        // K tile: 64 rows x 16 cols, split big/small (1 float4/thread)
        {
            int r = tid >> 2, c4 = (tid & 3) * 4;
            float4 v = *(const float4*)&Bk[(size_t)(bn + r)*DH_ + k0 + c4];
            float b0 = wmma::__float_to_tf32(v.x);
            float b1 = wmma::__float_to_tf32(v.y);
            float b2 = wmma::__float_to_tf32(v.z);
            float b3 = wmma::__float_to_tf32(v.w);
            Bb[r][c4+0]=b0; Bs[r][c4+0]=wmma::__float_to_tf32(v.x - b0);
            Bb[r][c4+1]=b1; Bs[r][c4+1]=wmma::__float_to_tf32(v.y - b1);
            Bb[r][c4+2]=b2; Bs[r][c4+2]=wmma::__float_to_tf32(v.z - b2);
            Bb[r][c4+3]=b3; Bs[r][c4+3]=wmma::__float_to_tf32(v.w - b3);
        }
        __syncthreads();
        #pragma unroll
        for (int kk = 0; kk < 16; kk += 8){
            wmma::fragment<wmma::matrix_a, 16, 16, 8, wmma::precision::tf32, wmma::row_major> ab[2], asm_[2];
            wmma::fragment<wmma::matrix_b, 16, 16, 8, wmma::precision::tf32, wmma::col_major> bb[2], bs[2];
            #pragma unroll
            for (int i = 0; i < 2; i++){
                wmma::load_matrix_sync(ab[i],   &Ab[wm + 16*i][kk], 20);
                wmma::load_matrix_sync(asm_[i], &As[wm + 16*i][kk], 20);
            }
            #pragma unroll
            for (int j = 0; j < 2; j++){
                // col_major: element (k,n) at mem[n*ld + k]; tile stored [n][k] row-major
                wmma::load_matrix_sync(bb[j], &Bb[wn + 16*j][kk], 20);
                wmma::load_matrix_sync(bs[j], &Bs[wn + 16*j][kk], 20);
            }
            #pragma unroll
            for (int i = 0; i < 2; i++)
                #pragma unroll
                for (int j = 0; j < 2; j++){
                    wmma::mma_sync(c[i][j], ab[i],   bb[j], c[i][j]);
                    wmma::mma_sync(c[i][j], ab[i],   bs[j], c[i][j]);
                    wmma::mma_sync(c[i][j], asm_[i], bb[j], c[i][j]);
                }
        }
        __syncthreads();
    }

    #pragma unroll
    for (int i = 0; i < 2; i++)
        #pragma unroll
        for (int j = 0; j < 2; j++)
            wmma::store_matrix_sync(&Sp[(size_t)(bm + wm + 16*i)*L_ + bn + wn + 16*j],
                                    c[i][j], L_, wmma::mem_row_major);
}

// ---------------- tf32 WMMA GEMM (PV: attn@V), CTA 128x64 ----------------
template<int EPI>
__global__ void __launch_bounds__(256)
gemm_tc(const float* __restrict__ A, const float* __restrict__ Bm,
        const float* __restrict__ bias, float* __restrict__ C, float scale,
        int Kt, int lda, int ldb, size_t sA, size_t sB)
{
    __shared__ union SmemU {
        struct { float As[128][16]; float Bs[16][72]; } s;
        float ep[128][72];
    } u;

    const int z = blockIdx.z;
    A  += (size_t)z * sA;
    Bm += (size_t)z * sB;
    const int bm = blockIdx.y * 128;
    const int bn = blockIdx.x * 64;
    const int tid = threadIdx.x;
    const int wid = tid >> 5;
    const int wm = (wid & 3) * 32;
    const int wn = (wid >> 2) * 32;

    wmma::fragment<wmma::accumulator, 16, 16, 8, float> c[2][2];
    #pragma unroll
    for (int i = 0; i < 2; i++)
        #pragma unroll
        for (int j = 0; j < 2; j++) wmma::fill_fragment(c[i][j], 0.f);

    for (int k0 = 0; k0 < Kt; k0 += 16){
        #pragma unroll
        for (int t = tid; t < 512; t += 256){
            int r = t >> 2, c4 = (t & 3) * 4;
            float4 v = *(const float4*)&A[(size_t)(bm + r)*lda + k0 + c4];
            u.s.As[r][c4+0] = wmma::__float_to_tf32(v.x);
            u.s.As[r][c4+1] = wmma::__float_to_tf32(v.y);
            u.s.As[r][c4+2] = wmma::__float_to_tf32(v.z);
            u.s.As[r][c4+3] = wmma::__float_to_tf32(v.w);
        }
        {
            int r = tid >> 4, c4 = (tid & 15) * 4;
            float4 v = *(const float4*)&Bm[(size_t)(k0 + r)*ldb + bn + c4];
            u.s.Bs[r][c4+0] = wmma::__float_to_tf32(v.x);
            u.s.Bs[r][c4+1] = wmma::__float_to_tf32(v.y);
            u.s.Bs[r][c4+2] = wmma::__float_to_tf32(v.z);
            u.s.Bs[r][c4+3] = wmma::__float_to_tf32(v.w);
        }
        __syncthreads();
        #pragma unroll
        for (int kk = 0; kk < 16; kk += 8){
            wmma::fragment<wmma::matrix_a, 16, 16, 8, wmma::precision::tf32, wmma::row_major> a[2];
            wmma::fragment<wmma::matrix_b, 16, 16, 8, wmma::precision::tf32, wmma::row_major> b[2];
            #pragma unroll
            for (int i = 0; i < 2; i++)
                wmma::load_matrix_sync(a[i], &u.s.As[wm + 16*i][kk], 16);
            #pragma unroll
            for (int j = 0; j < 2; j++)
                wmma::load_matrix_sync(b[j], &u.s.Bs[kk][wn + 16*j], 72);
            #pragma unroll
            for (int i = 0; i < 2; i++)
                #pragma unroll
                for (int j = 0; j < 2; j++)
                    wmma::mma_sync(c[i][j], a[i], b[j], c[i][j]);
        }
        __syncthreads();
    }

    #pragma unroll
    for (int i = 0; i < 2; i++)
        #pragma unroll
        for (int j = 0; j < 2; j++)
            wmma::store_matrix_sync(&u.ep[wm + 16*i][wn + 16*j], c[i][j], 72, wmma::mem_row_major);
    __syncthreads();

    #pragma unroll
    for (int t = tid; t < 128*64; t += 256){
        const int r = t >> 6, cc = t & 63;
        const int m = bm + r, n = bn + cc;
        float v = u.ep[r][cc];
        if (bias) v += bias[n];
        v *= scale;
        if (EPI == 0){
            C[(size_t)m*D_ + n] = v;
        } else if (EPI == 1){
            const int b = m >> 10, l = m & (L_-1);
            const int h = n >> 6,  dh = n & (DH_-1);
            C[((size_t)(b*H_+h)*L_ + l)*DH_ + dh] = v;
        } else {
            const int b = z >> 4, h = z & (H_-1);
            C[((size_t)(b*L_ + m))*D_ + h*DH_ + cc] = v;
        }
    }
}

// ---------------- qsk[b,h,q,s] = sum_d Q[bh,q,d]*Wsk[s,d]; slot 30 = Q·bsk ----------------
__global__ void qsk_k(const float* __restrict__ Wsk, const float* __restrict__ bsk){
    const int s   = threadIdx.x;
    const int row = blockIdx.x*8 + threadIdx.y;
    if (s >= 31) return;
    const float* qp = g_Q + (size_t)row * DH_;
    const float* wp = (s < SD_) ? (Wsk + s*DH_) : bsk;
    float a = 0.f;
    #pragma unroll
    for (int d = 0; d < DH_; d++) a += qp[d]*wp[d];
    g_qsk[(size_t)row*31 + s] = a;
}

// ---------------- scores += ALPHA*(struct·qsk + q·bsk); apply masks ----------------
__global__ void __launch_bounds__(256)
bias_mask_k(const float* __restrict__ st, const void* __restrict__ mask,
            const void* __restrict__ kpm)
{
    const int b = blockIdx.z, q = blockIdx.y;
    const int k = blockIdx.x*256 + threadIdx.x;
    const int tid = threadIdx.x;
    __shared__ float qs[H_][32];
    for (int t = tid; t < H_*31; t += 256){
        int h = t/31, s = t%31;
        qs[h][s] = g_qsk[((size_t)((b*H_+h)*L_ + q))*31 + s];
    }
    __syncthreads();
    const int fm = g_flags[0] ? 2 : (g_flags[1] ? 0 : 1);
    const bool masked = mread(kpm, (size_t)b*L_ + k, fm)
                     || mread(mask, ((size_t)(b*L_+q))*L_ + k, fm);
    float r[SD_];
    const float* sp = st + ((size_t)((b*L_+q))*L_ + k) * SD_;
    #pragma unroll
    for (int i = 0; i < 15; i++){
        float2 u = *(const float2*)(sp + 2*i);
        r[2*i] = u.x; r[2*i+1] = u.y;
    }
    #pragma unroll
    for (int h = 0; h < H_; h++){
        float a = qs[h][30];
        #pragma unroll
        for (int s = 0; s < SD_; s++) a += qs[h][s]*r[s];
        size_t si = ((size_t)((b*H_+h)*L_ + q))*L_ + k;
        float val = g_S[si] + a;             // ALPHA = 1
        g_S[si] = masked ? -1e18f : val;
    }
}

// ---------------- row softmax over k; stream head-0 rows to top_attn ----------------
__global__ void __launch_bounds__(256)
softmax_k(float* __restrict__ top){
    const int row = blockIdx.x;
    const int bh = row >> 10, q = row & (L_-1);
    float* p = g_S + (size_t)row * L_;
    const int tid = threadIdx.x;
    float v[4];
    float mx = -3.4e38f;
    #pragma unroll
    for (int i=0;i<4;i++){ v[i] = p[tid + i*256]; mx = fmaxf(mx, v[i]); }
    __shared__ float red[8];
    #pragma unroll
    for (int o=16;o>0;o>>=1) mx = fmaxf(mx, __shfl_xor_sync(0xffffffffu, mx, o));
    if ((tid & 31) == 0) red[tid>>5] = mx;
    __syncthreads();
    float m2 = red[0];
    #pragma unroll
    for (int i=1;i<8;i++) m2 = fmaxf(m2, red[i]);
    float sum = 0.f;
    #pragma unroll
    for (int i=0;i<4;i++){ v[i] = __expf(v[i]-m2); sum += v[i]; }
    __syncthreads();
    #pragma unroll
    for (int o=16;o>0;o>>=1) sum += __shfl_xor_sync(0xffffffffu, sum, o);
    if ((tid & 31) == 0) red[tid>>5] = sum;
    __syncthreads();
    float s2 = 0.f;
    #pragma unroll
    for (int i=0;i<8;i++) s2 += red[i];
    const float inv = 1.f / s2;
    const bool isTop = (bh & (H_-1)) == 0;
    float* tp = top + ((size_t)((bh>>4)*L_ + q))*L_;
    #pragma unroll
    for (int i=0;i<4;i++){
        float a = v[i]*inv;
        p[tid + i*256] = a;
        if (isTop) tp[tid + i*256] = a;
    }
}

// ---------------- sattn[b,h,q,s] = sum_k attn[bh,q,k]*struct[b,q,k,s] ----------------
__global__ void __launch_bounds__(256)
sattn_k(const float* __restrict__ st){
    const int bq = blockIdx.x;
    const int b = bq >> 10, q = bq & (L_-1);
    const int tid = threadIdx.x;
    const int h = tid/15, sp = tid%15;
    const bool act = tid < 240;
    float a0 = 0.f, a1 = 0.f;
    __shared__ float attn_s[H_][256];
    for (int kt = 0; kt < L_; kt += 256){
        __syncthreads();
        for (int i = tid; i < H_*256; i += 256){
            int hh = i>>8, kk = i&255;
            attn_s[hh][kk] = g_S[((size_t)((b*H_+hh)*L_ + q))*L_ + kt + kk];
        }
        __syncthreads();
        if (act){
            const float* s2 = st + ((size_t)(bq)*L_ + kt)*SD_ + sp*2;
            #pragma unroll 4
            for (int kk = 0; kk < 256; kk++){
                float av = attn_s[h][kk];
                float2 u = __ldg((const float2*)(s2 + (size_t)kk*SD_));
                a0 += av*u.x; a1 += av*u.y;
            }
        }
    }
    if (act){
        size_t o = ((size_t)((b*H_+h)*L_ + q))*SD_ + sp*2;
        g_sattn[o] = a0; g_sattn[o+1] = a1;
    }
}

// ---------------- ctx += BETA*(sattn @ Wsv + bsv)  (sum attn = 1) ----------------
__global__ void __launch_bounds__(256)
addctx_k(const float* __restrict__ Wsv, const float* __restrict__ bsv){
    const int bq = blockIdx.x;
    const int b = bq >> 10, q = bq & (L_-1);
    const int tid = threadIdx.x;
    __shared__ float sa[H_][SD_];
    for (int i = tid; i < H_*SD_; i += 256){
        int h = i/SD_, s = i%SD_;
        sa[h][s] = g_sattn[((size_t)((b*H_+h)*L_ + q))*SD_ + s];
    }
    __syncthreads();
    #pragma unroll
    for (int rep = 0; rep < 4; rep++){
        int hd = rep*256 + tid;
        int h = hd >> 6, d = hd & (DH_-1);
        float a = bsv[d];
        #pragma unroll
        for (int s = 0; s < SD_; s++) a += sa[h][s]*Wsv[s*DH_+d];
        g_ctx[(size_t)bq*D_ + hd] += a;      // BETA = 1
    }
}

// ---------------- launcher ----------------
extern "C" void kernel_launch(void* const* d_in, const int* in_sizes, int n_in,
                              void* d_out, int out_size)
{
    const float* key       = (const float*)d_in[0];
    const float* value     = (const float*)d_in[1];
    const float* query     = (const float*)d_in[2];
    const float* structure = (const float*)d_in[3];
    const void*  mask      = d_in[4];
    const void*  kpm       = d_in[5];
    const float* Wq  = (const float*)d_in[6];
    const float* bq  = (const float*)d_in[7];
    const float* Wk  = (const float*)d_in[8];
    const float* bk  = (const float*)d_in[9];
    const float* Wv  = (const float*)d_in[10];
    const float* bv  = (const float*)d_in[11];
    const float* Wsk = (const float*)d_in[12];
    const float* bsk = (const float*)d_in[13];
    const float* Wsv = (const float*)d_in[14];
    const float* bsv = (const float*)d_in[15];
    const float* Wo  = (const float*)d_in[16];
    const float* bo  = (const float*)d_in[17];

    float* out = (float*)d_out;
    float* top = out + (size_t)B_*L_*D_;

    float *pQ, *pK, *pV, *pS, *pCtx;
    cudaGetSymbolAddress((void**)&pQ,   g_Q);
    cudaGetSymbolAddress((void**)&pK,   g_K);
    cudaGetSymbolAddress((void**)&pV,   g_V);
    cudaGetSymbolAddress((void**)&pS,   g_S);
    cudaGetSymbolAddress((void**)&pCtx, g_ctx);

    // mask dtype detection
    reset_flags_k<<<1,1>>>();
    detect_k<<<2048,256>>>((const unsigned*)mask, B_*L_*L_/4);

    // QKV projections (v2 tc; EPI=1 scatter); Q pre-scaled by 1/sqrt(dh)
    dim3 gtc2(D_/128, (B_*L_)/128, 1);
    gemm_tc2<1><<<gtc2,256>>>(query, Wq, bq, pQ, 0.125f);
    gemm_tc2<1><<<gtc2,256>>>(key,   Wk, bk, pK, 1.0f);
    gemm_tc2<1><<<gtc2,256>>>(value, Wv, bv, pV, 1.0f);

    // qsk = Q @ Wsk^T (+ Q·bsk in slot 30)
    qsk_k<<<(B_*H_*L_)/8, dim3(32,8)>>>(Wsk, bsk);

    // scores = Q @ K^T, 3xTF32 tensor cores (near-fp32 precision)
    qk_tc<<<dim3(L_/64, L_/128, B_*H_),256>>>(pQ, pK, pS);

    // + struct bias, masks
    bias_mask_k<<<dim3(L_/256, L_, B_),256>>>(structure, mask, kpm);

    // softmax (writes attn in place, head-0 rows to top_attn)
    softmax_k<<<B_*H_*L_,256>>>(top);

    // ctx = attn @ V, tf32 tensor cores (EPI=2 scatter), batched over bh
    gemm_tc<2><<<dim3(1, L_/128, B_*H_),256>>>(
        pS, pV, (const float*)nullptr, pCtx, 1.0f,
        L_, L_, DH_, (size_t)L_*L_, (size_t)L_*DH_);

    // sattn = attn @ struct ; ctx += sattn @ Wsv + bsv
    sattn_k<<<B_*L_,256>>>(structure);
    addctx_k<<<B_*L_,256>>>(Wsv, bsv);

    // output = ctx @ Wo + bo (v2 tc)
    gemm_tc2<0><<<gtc2,256>>>(pCtx, Wo, bo, out, 1.0f);
}